// round 3
// baseline (speedup 1.0000x reference)
#include <cuda_runtime.h>

#define N_TOK 343
#define BATCH 256
#define HEADS 6
#define HDIM  32
#define CDIM  192
#define ODIM  576            // 3*C
#define MROWS 87808          // BATCH*N_TOK
#define NN2   117649         // 343*343
#define SCALE 0.17677669529663687f
#define NEGBIG (-1e30f)

// ---------------- scratch (device globals: no runtime allocation allowed) ----
__device__ float g_qkv[(size_t)MROWS * ODIM];   // [B*N, 3C]  (~202 MB)
__device__ float g_att[(size_t)MROWS * CDIM];   // [B*N, C]   (~67 MB)
__device__ float g_bias[HEADS * NN2];           // [H, N, N]  (~2.8 MB)

// ---------------- kernel 1: gather relative-position bias ------------------
__global__ void bias_gather_kernel(const float* __restrict__ tab,
                                   const int* __restrict__ idx) {
    int p = blockIdx.x * 256 + threadIdx.x;
    if (p < NN2) {
        int id = idx[p];
        #pragma unroll
        for (int h = 0; h < HEADS; h++)
            g_bias[h * NN2 + p] = tab[id * HEADS + h];
    }
}

// ---------------- GEMM: out[m][o] = sum_c A[m][c]*W[o][c] (+bias) ----------
// 128x64 CTA tile, 128 threads, 8x8 per thread, K staged in 16-chunks.
__device__ __forceinline__ void gemm_body(const float* __restrict__ A,
                                          const float* __restrict__ W,
                                          const float* __restrict__ bias,
                                          float* __restrict__ out,
                                          int ocols) {
    __shared__ float As[16][128];
    __shared__ float Bs[16][64];
    const int t  = threadIdx.x;
    const int m0 = blockIdx.x * 128;
    const int o0 = blockIdx.y * 64;
    const int tx = t & 7;
    const int ty = t >> 3;

    float acc[8][8];
    #pragma unroll
    for (int i = 0; i < 8; i++)
        #pragma unroll
        for (int j = 0; j < 8; j++) acc[i][j] = 0.f;

    const int brow = o0 + (t >> 1);
    const int bco  = (t & 1) * 2;     // float4 index base: 0 or 2

    for (int k0 = 0; k0 < CDIM; k0 += 16) {
        const float* arow = A + (size_t)(m0 + t) * CDIM + k0;
        float4 a0 = *(const float4*)(arow + 0);
        float4 a1 = *(const float4*)(arow + 4);
        float4 a2 = *(const float4*)(arow + 8);
        float4 a3 = *(const float4*)(arow + 12);
        const float* wrow = W + (size_t)brow * CDIM + k0 + bco * 4;
        float4 w0 = *(const float4*)(wrow + 0);
        float4 w1 = *(const float4*)(wrow + 4);
        __syncthreads();
        As[0][t]  = a0.x; As[1][t]  = a0.y; As[2][t]  = a0.z; As[3][t]  = a0.w;
        As[4][t]  = a1.x; As[5][t]  = a1.y; As[6][t]  = a1.z; As[7][t]  = a1.w;
        As[8][t]  = a2.x; As[9][t]  = a2.y; As[10][t] = a2.z; As[11][t] = a2.w;
        As[12][t] = a3.x; As[13][t] = a3.y; As[14][t] = a3.z; As[15][t] = a3.w;
        {
            int kk = bco * 4;
            int oo = t >> 1;
            Bs[kk + 0][oo] = w0.x; Bs[kk + 1][oo] = w0.y;
            Bs[kk + 2][oo] = w0.z; Bs[kk + 3][oo] = w0.w;
            Bs[kk + 4][oo] = w1.x; Bs[kk + 5][oo] = w1.y;
            Bs[kk + 6][oo] = w1.z; Bs[kk + 7][oo] = w1.w;
        }
        __syncthreads();
        #pragma unroll
        for (int k = 0; k < 16; k++) {
            float av[8], bv[8];
            *(float4*)&av[0] = *(const float4*)&As[k][ty * 8];
            *(float4*)&av[4] = *(const float4*)&As[k][ty * 8 + 4];
            *(float4*)&bv[0] = *(const float4*)&Bs[k][tx * 8];
            *(float4*)&bv[4] = *(const float4*)&Bs[k][tx * 8 + 4];
            #pragma unroll
            for (int i = 0; i < 8; i++)
                #pragma unroll
                for (int j = 0; j < 8; j++)
                    acc[i][j] += av[i] * bv[j];
        }
    }

    float bb[8];
    #pragma unroll
    for (int j = 0; j < 8; j++) bb[j] = bias ? bias[o0 + tx * 8 + j] : 0.f;

    #pragma unroll
    for (int i = 0; i < 8; i++) {
        size_t m = (size_t)(m0 + ty * 8 + i);
        float4 v0 = make_float4(acc[i][0] + bb[0], acc[i][1] + bb[1],
                                acc[i][2] + bb[2], acc[i][3] + bb[3]);
        float4 v1 = make_float4(acc[i][4] + bb[4], acc[i][5] + bb[5],
                                acc[i][6] + bb[6], acc[i][7] + bb[7]);
        *(float4*)&out[m * ocols + o0 + tx * 8]     = v0;
        *(float4*)&out[m * ocols + o0 + tx * 8 + 4] = v1;
    }
}

__global__ __launch_bounds__(128) void gemm_qkv_kernel(const float* __restrict__ x,
                                                       const float* __restrict__ w) {
    gemm_body(x, w, nullptr, g_qkv, ODIM);
}

__global__ __launch_bounds__(128) void gemm_proj_kernel(const float* __restrict__ w,
                                                        const float* __restrict__ b,
                                                        float* __restrict__ out) {
    gemm_body(g_att, w, b, out, CDIM);
}

// ---------------- kernel 3: fused windowed attention (flash-style) ---------
// Per CTA: one (b, h, 128-query tile). Streams 64-key tiles with online
// softmax. bias+mask are pre-staged into the P buffer (coalesced loads).
__global__ __launch_bounds__(256, 2) void attn_kernel(const float* __restrict__ mask) {
    extern __shared__ float smf[];
    float* Qs  = smf;          // [32][128]  d-major
    float* Ks  = smf + 4096;   // [32][64]   d-major
    float* Vs  = smf + 6144;   // [64][32]
    float* Ps  = smf + 8192;   // [128][68]  (bias+mask, then P)
    float* Asm = smf + 16896;  // [128] per-row alpha
    float* Lsm = smf + 17024;  // [128] per-row l

    const int t  = threadIdx.x;
    const int q0 = blockIdx.x * 128;
    const int h  = blockIdx.y;
    const int b  = blockIdx.z;
    const int w  = b & 63;     // window id = b % NW

    const float* qptr = g_qkv + (size_t)b * N_TOK * ODIM + h * HDIM;
    const float* kptr = qptr + CDIM;
    const float* vptr = qptr + 2 * CDIM;
    const float* mrow = mask  + (size_t)w * NN2;
    const float* brow = g_bias + (size_t)h * NN2;

    const int tx  = t & 15;    // S-phase col group
    const int ty  = t >> 4;    // S-phase row group (8 rows each)
    const int pry = t >> 3;    // PV-phase row group (4 rows each)
    const int pc  = t & 7;     // PV-phase col group (4 cols each)

    // ---- load Q tile, transposed to d-major ----
    {
        int i  = t >> 1;             // 0..127
        int qi = q0 + i;
        int hb = (t & 1) * 16;
        #pragma unroll
        for (int c = 0; c < 4; c++) {
            float4 v = make_float4(0.f, 0.f, 0.f, 0.f);
            if (qi < N_TOK)
                v = *(const float4*)(qptr + (size_t)qi * ODIM + hb + c * 4);
            int d = hb + c * 4;
            Qs[(d + 0) * 128 + i] = v.x;
            Qs[(d + 1) * 128 + i] = v.y;
            Qs[(d + 2) * 128 + i] = v.z;
            Qs[(d + 3) * 128 + i] = v.w;
        }
    }

    float mrun[8], lrun[8];
    #pragma unroll
    for (int i = 0; i < 8; i++) { mrun[i] = NEGBIG; lrun[i] = 0.f; }
    float o[4][4];
    #pragma unroll
    for (int i = 0; i < 4; i++)
        #pragma unroll
        for (int c = 0; c < 4; c++) o[i][c] = 0.f;

    for (int k0 = 0; k0 < N_TOK; k0 += 64) {
        __syncthreads();   // prior PV (and Q staging) complete

        // ---- K (d-major) and V tiles, zero-filled past N ----
        {
            int j  = t >> 2;               // 0..63
            int kj = k0 + j;
            bool valid = kj < N_TOK;
            int fb = (t & 3) * 2;
            #pragma unroll
            for (int c = 0; c < 2; c++) {
                int f = fb + c;
                float4 kv = make_float4(0.f, 0.f, 0.f, 0.f);
                float4 vv = make_float4(0.f, 0.f, 0.f, 0.f);
                if (valid) {
                    kv = *(const float4*)(kptr + (size_t)kj * ODIM + f * 4);
                    vv = *(const float4*)(vptr + (size_t)kj * ODIM + f * 4);
                }
                int d = f * 4;
                Ks[(d + 0) * 64 + j] = kv.x;
                Ks[(d + 1) * 64 + j] = kv.y;
                Ks[(d + 2) * 64 + j] = kv.z;
                Ks[(d + 3) * 64 + j] = kv.w;
                *(float4*)&Vs[j * 32 + d] = vv;
            }
        }

        // ---- stage bias+mask into Ps (coalesced) ----
        #pragma unroll 8
        for (int u = 0; u < 32; u++) {
            int e  = u * 256 + t;
            int r  = e >> 6;
            int jc = e & 63;
            int qi = q0 + r;
            int kj = k0 + jc;
            float bm;
            if (qi >= N_TOK)      bm = 0.f;
            else if (kj >= N_TOK) bm = NEGBIG;
            else                  bm = brow[qi * N_TOK + kj] + mrow[qi * N_TOK + kj];
            Ps[r * 68 + jc] = bm;
        }
        __syncthreads();

        // ---- S = Q K^T (8x4 per thread) ----
        float s[8][4];
        #pragma unroll
        for (int i = 0; i < 8; i++)
            #pragma unroll
            for (int j = 0; j < 4; j++) s[i][j] = 0.f;

        #pragma unroll 8
        for (int d = 0; d < 32; d++) {
            float4 a0 = *(const float4*)&Qs[d * 128 + ty * 8];
            float4 a1 = *(const float4*)&Qs[d * 128 + ty * 8 + 4];
            float4 kv = *(const float4*)&Ks[d * 64 + tx * 4];
            float av[8] = {a0.x, a0.y, a0.z, a0.w, a1.x, a1.y, a1.z, a1.w};
            #pragma unroll
            for (int i = 0; i < 8; i++) {
                s[i][0] += av[i] * kv.x;
                s[i][1] += av[i] * kv.y;
                s[i][2] += av[i] * kv.z;
                s[i][3] += av[i] * kv.w;
            }
        }

        // ---- online softmax; P overwrites bias+mask (same owner thread) ----
        #pragma unroll
        for (int i = 0; i < 8; i++) {
            int r = ty * 8 + i;
            float sv0 = s[i][0] * SCALE + Ps[r * 68 + tx * 4 + 0];
            float sv1 = s[i][1] * SCALE + Ps[r * 68 + tx * 4 + 1];
            float sv2 = s[i][2] * SCALE + Ps[r * 68 + tx * 4 + 2];
            float sv3 = s[i][3] * SCALE + Ps[r * 68 + tx * 4 + 3];
            float tm = fmaxf(fmaxf(sv0, sv1), fmaxf(sv2, sv3));
            tm = fmaxf(tm, __shfl_xor_sync(0xffffffffu, tm, 1));
            tm = fmaxf(tm, __shfl_xor_sync(0xffffffffu, tm, 2));
            tm = fmaxf(tm, __shfl_xor_sync(0xffffffffu, tm, 4));
            tm = fmaxf(tm, __shfl_xor_sync(0xffffffffu, tm, 8));
            float mn = fmaxf(mrun[i], tm);
            float al = __expf(mrun[i] - mn);
            mrun[i] = mn;
            float4 p;
            p.x = __expf(sv0 - mn);
            p.y = __expf(sv1 - mn);
            p.z = __expf(sv2 - mn);
            p.w = __expf(sv3 - mn);
            float ts = (p.x + p.y) + (p.z + p.w);
            ts += __shfl_xor_sync(0xffffffffu, ts, 1);
            ts += __shfl_xor_sync(0xffffffffu, ts, 2);
            ts += __shfl_xor_sync(0xffffffffu, ts, 4);
            ts += __shfl_xor_sync(0xffffffffu, ts, 8);
            lrun[i] = lrun[i] * al + ts;
            *(float4*)&Ps[r * 68 + tx * 4] = p;
            if (tx == 0) Asm[r] = al;
        }
        __syncthreads();

        // ---- O = O*alpha + P V (4x4 per thread) ----
        {
            float al4[4];
            #pragma unroll
            for (int i = 0; i < 4; i++) al4[i] = Asm[pry * 4 + i];
            #pragma unroll
            for (int i = 0; i < 4; i++)
                #pragma unroll
                for (int c = 0; c < 4; c++) o[i][c] *= al4[i];

            #pragma unroll 8
            for (int j = 0; j < 64; j++) {
                float4 vv = *(const float4*)&Vs[j * 32 + pc * 4];
                #pragma unroll
                for (int i = 0; i < 4; i++) {
                    float p = Ps[(pry * 4 + i) * 68 + j];
                    o[i][0] += p * vv.x;
                    o[i][1] += p * vv.y;
                    o[i][2] += p * vv.z;
                    o[i][3] += p * vv.w;
                }
            }
        }
    }

    // ---- publish per-row l, normalize, store to [b, n, h, d] layout ----
    if (tx == 0) {
        #pragma unroll
        for (int i = 0; i < 8; i++) Lsm[ty * 8 + i] = lrun[i];
    }
    __syncthreads();

    #pragma unroll
    for (int i = 0; i < 4; i++) {
        int r  = pry * 4 + i;
        int qi = q0 + r;
        if (qi < N_TOK) {
            float inv = 1.f / Lsm[r];
            float4 ov = make_float4(o[i][0] * inv, o[i][1] * inv,
                                    o[i][2] * inv, o[i][3] * inv);
            *(float4*)&g_att[((size_t)b * N_TOK + qi) * CDIM + h * HDIM + pc * 4] = ov;
        }
    }
}

// ---------------- launch ----------------------------------------------------
extern "C" void kernel_launch(void* const* d_in, const int* in_sizes, int n_in,
                              void* d_out, int out_size) {
    (void)in_sizes; (void)n_in; (void)out_size;
    const float* x        = (const float*)d_in[0];
    const float* mask     = (const float*)d_in[1];
    const float* qkv_w    = (const float*)d_in[2];
    const float* proj_w   = (const float*)d_in[3];
    const float* proj_b   = (const float*)d_in[4];
    const float* bias_tab = (const float*)d_in[5];
    const int*   rel_idx  = (const int*)d_in[6];
    float* out = (float*)d_out;

    // 68608 B dynamic smem > 48 KB default: opt in (idempotent, non-stream call)
    cudaFuncSetAttribute(attn_kernel,
                         cudaFuncAttributeMaxDynamicSharedMemorySize, 68608);

    bias_gather_kernel<<<(NN2 + 255) / 256, 256>>>(bias_tab, rel_idx);
    gemm_qkv_kernel<<<dim3(MROWS / 128, ODIM / 64), 128>>>(x, qkv_w);
    attn_kernel<<<dim3(3, HEADS, BATCH), 256, 68608>>>(mask);
    gemm_proj_kernel<<<dim3(MROWS / 128, CDIM / 64), 128>>>(proj_w, proj_b, out);
}

// round 6
// speedup vs baseline: 1.1217x; 1.1217x over previous
#include <cuda_runtime.h>
#include <cstdint>

#define N_TOK 343
#define BATCH 256
#define HEADS 6
#define HDIM  32
#define CDIM  192
#define ODIM  576            // 3*C
#define MROWS 87808          // BATCH*N_TOK
#define NN2   117649         // 343*343
#define SCALE 0.17677669529663687f
#define NEGBIG (-1e30f)

// ---------------- scratch (device globals: no runtime allocation allowed) ----
// NOTE: these symbols must ONLY be referenced from device code. Referencing
// them in host code yields the host shadow address (ATS-valid on GB300, so it
// silently writes host memory instead of the device array — R5's bug).
__device__ float g_qkv[(size_t)MROWS * ODIM];   // [B*N, 3C]
__device__ float g_att[(size_t)MROWS * CDIM];   // [B*N, C]
__device__ float g_bias[HEADS * NN2];           // [H, N, N]

// ---------------- kernel 1: gather relative-position bias ------------------
__global__ void bias_gather_kernel(const float* __restrict__ tab,
                                   const int* __restrict__ idx) {
    int p = blockIdx.x * 256 + threadIdx.x;
    if (p < NN2) {
        int id = idx[p];
        #pragma unroll
        for (int h = 0; h < HEADS; h++)
            g_bias[h * NN2 + p] = tab[id * HEADS + h];
    }
}

// ================= tensor-core GEMM via mma.sync (tf32) =====================
// out[m][o] = sum_c A[m][c] * W[o][c] (+bias[o]).
// CTA tile 128(M) x 64(N), K=192 in 2 chunks of 96. 8 warps: 4(M) x 2(N),
// warp tile 32x32 = 2x4 m16n8k8 MMAs per k-step, 12 k-steps per chunk.
// SMEM holds tf32-converted tiles in FRAGMENT ORDER so fragment loads are
// a single LDS.128 (A) / LDS.64 (B) per thread, conflict-free.

#define GK  192
#define GBK 96
#define NST 12                 // k-steps per chunk

__device__ __forceinline__ float to_tf32(float x) {
    uint32_t u;
    asm("cvt.rna.tf32.f32 %0, %1;" : "=r"(u) : "f"(x));
    return __uint_as_float(u);
}

__device__ __forceinline__ void mma_tf32(float* d, const uint32_t* a, const uint32_t* b) {
    asm volatile(
        "mma.sync.aligned.m16n8k8.row.col.f32.tf32.tf32.f32 "
        "{%0,%1,%2,%3}, {%4,%5,%6,%7}, {%8,%9}, {%0,%1,%2,%3};\n"
        : "+f"(d[0]), "+f"(d[1]), "+f"(d[2]), "+f"(d[3])
        : "r"(a[0]), "r"(a[1]), "r"(a[2]), "r"(a[3]), "r"(b[0]), "r"(b[1]));
}

// As: 8 m-blocks x 12 steps x 32 lanes x 4 regs = 12288 floats
// Bs: 8 n-blocks x 12 steps x 32 lanes x 2 regs =  6144 floats
#define SM_GEMM_FLOATS (12288 + 6144)      // 73728 bytes

// DST=0: A = x param,        out = g_qkv (device symbol)
// DST=1: A = g_att (symbol), out = out param (d_out)
template <int DST>
__global__ __launch_bounds__(256, 2)
void gemm_tc(const float* __restrict__ Ain, const float* __restrict__ W,
             const float* __restrict__ bias, float* __restrict__ outp, int ocols) {
    const float* A   = (DST == 0) ? Ain : (const float*)g_att;
    float*       out = (DST == 0) ? (float*)g_qkv : outp;

    extern __shared__ float sm[];
    float* As = sm;            // 12288 floats
    float* Bs = sm + 12288;    // 6144 floats

    const int t    = threadIdx.x;
    const int lane = t & 31;
    const int wid  = t >> 5;
    const int o0   = blockIdx.x * 64;
    const int m0   = blockIdx.y * 128;
    const int wr   = wid >> 1;        // warp M index (0..3)
    const int wc   = wid & 1;         // warp N index (0..1)

    float acc[2][4][4];
    #pragma unroll
    for (int im = 0; im < 2; im++)
        #pragma unroll
        for (int jn = 0; jn < 4; jn++)
            #pragma unroll
            for (int q = 0; q < 4; q++) acc[im][jn][q] = 0.f;

    for (int chunk = 0; chunk < 2; chunk++) {
        const int k0 = chunk * GBK;
        __syncthreads();   // previous chunk's compute done before overwrite

        // ---- stage A [128 x 96] into fragment order (tf32) ----
        #pragma unroll
        for (int u = 0; u < 12; u++) {
            int e = u * 256 + t;          // 0..3071
            int r = e / 24;               // row 0..127
            int c = (e % 24) * 4;         // col (mult of 4)
            float4 v = *(const float4*)(A + (size_t)(m0 + r) * GK + k0 + c);
            int grp = r & 7, hm = (r >> 3) & 1, mb = r >> 4;
            int s = c >> 3, hk = (c >> 2) & 1;
            int base = (((mb * NST + s) * 32) + grp * 4) * 4 + hm + 2 * hk;
            As[base + 0]  = to_tf32(v.x);
            As[base + 4]  = to_tf32(v.y);
            As[base + 8]  = to_tf32(v.z);
            As[base + 12] = to_tf32(v.w);
        }
        // ---- stage B [64 x 96] into fragment order (tf32) ----
        #pragma unroll
        for (int u = 0; u < 6; u++) {
            int e = u * 256 + t;          // 0..1535
            int j = e / 24;               // n row 0..63
            int c = (e % 24) * 4;
            float4 v = *(const float4*)(W + (size_t)(o0 + j) * GK + k0 + c);
            int grp = j & 7, nb = j >> 3;
            int s = c >> 3, hk = (c >> 2) & 1;
            int base = (((nb * NST + s) * 32) + grp * 4) * 2 + hk;
            Bs[base + 0] = to_tf32(v.x);
            Bs[base + 2] = to_tf32(v.y);
            Bs[base + 4] = to_tf32(v.z);
            Bs[base + 6] = to_tf32(v.w);
        }
        __syncthreads();

        // ---- 12 k-steps of m16n8k8 ----
        #pragma unroll
        for (int s = 0; s < NST; s++) {
            uint32_t a[2][4];
            #pragma unroll
            for (int im = 0; im < 2; im++) {
                const uint4 av = *(const uint4*)&As[(((wr * 2 + im) * NST + s) * 32 + lane) * 4];
                a[im][0] = av.x; a[im][1] = av.y; a[im][2] = av.z; a[im][3] = av.w;
            }
            uint32_t b[4][2];
            #pragma unroll
            for (int jn = 0; jn < 4; jn++) {
                const uint2 bv = *(const uint2*)&Bs[(((wc * 4 + jn) * NST + s) * 32 + lane) * 2];
                b[jn][0] = bv.x; b[jn][1] = bv.y;
            }
            #pragma unroll
            for (int im = 0; im < 2; im++)
                #pragma unroll
                for (int jn = 0; jn < 4; jn++)
                    mma_tf32(acc[im][jn], a[im], b[jn]);
        }
    }

    // ---- epilogue: D fragment -> gmem (+bias) ----
    const int grp = lane >> 2;
    const int tig = lane & 3;
    #pragma unroll
    for (int im = 0; im < 2; im++) {
        #pragma unroll
        for (int jn = 0; jn < 4; jn++) {
            int col = o0 + wc * 32 + jn * 8 + tig * 2;
            float b0 = 0.f, b1 = 0.f;
            if (bias) { b0 = bias[col]; b1 = bias[col + 1]; }
            int row0 = m0 + wr * 32 + im * 16 + grp;
            float2 v0 = make_float2(acc[im][jn][0] + b0, acc[im][jn][1] + b1);
            float2 v1 = make_float2(acc[im][jn][2] + b0, acc[im][jn][3] + b1);
            *(float2*)(out + (size_t)row0 * ocols + col)       = v0;
            *(float2*)(out + (size_t)(row0 + 8) * ocols + col) = v1;
        }
    }
}

// ---------------- kernel 3: fused windowed attention (flash-style) ---------
__global__ __launch_bounds__(256, 2) void attn_kernel(const float* __restrict__ mask) {
    extern __shared__ float smf[];
    float* Qs  = smf;          // [32][128]  d-major
    float* Ks  = smf + 4096;   // [32][64]   d-major
    float* Vs  = smf + 6144;   // [64][32]
    float* Ps  = smf + 8192;   // [128][68]  (bias+mask, then P)
    float* Asm = smf + 16896;  // [128] per-row alpha
    float* Lsm = smf + 17024;  // [128] per-row l

    const int t  = threadIdx.x;
    const int q0 = blockIdx.x * 128;
    const int h  = blockIdx.y;
    const int b  = blockIdx.z;
    const int w  = b & 63;     // window id = b % NW

    const float* qptr = g_qkv + (size_t)b * N_TOK * ODIM + h * HDIM;
    const float* kptr = qptr + CDIM;
    const float* vptr = qptr + 2 * CDIM;
    const float* mrow = mask  + (size_t)w * NN2;
    const float* brow = g_bias + (size_t)h * NN2;

    const int tx  = t & 15;    // S-phase col group
    const int ty  = t >> 4;    // S-phase row group (8 rows each)
    const int pry = t >> 3;    // PV-phase row group (4 rows each)
    const int pc  = t & 7;     // PV-phase col group (4 cols each)

    // ---- load Q tile, transposed to d-major ----
    {
        int i  = t >> 1;             // 0..127
        int qi = q0 + i;
        int hb = (t & 1) * 16;
        #pragma unroll
        for (int c = 0; c < 4; c++) {
            float4 v = make_float4(0.f, 0.f, 0.f, 0.f);
            if (qi < N_TOK)
                v = *(const float4*)(qptr + (size_t)qi * ODIM + hb + c * 4);
            int d = hb + c * 4;
            Qs[(d + 0) * 128 + i] = v.x;
            Qs[(d + 1) * 128 + i] = v.y;
            Qs[(d + 2) * 128 + i] = v.z;
            Qs[(d + 3) * 128 + i] = v.w;
        }
    }

    float mrun[8], lrun[8];
    #pragma unroll
    for (int i = 0; i < 8; i++) { mrun[i] = NEGBIG; lrun[i] = 0.f; }
    float o[4][4];
    #pragma unroll
    for (int i = 0; i < 4; i++)
        #pragma unroll
        for (int c = 0; c < 4; c++) o[i][c] = 0.f;

    for (int k0 = 0; k0 < N_TOK; k0 += 64) {
        __syncthreads();   // prior PV (and Q staging) complete

        // ---- K (d-major) and V tiles, zero-filled past N ----
        {
            int j  = t >> 2;               // 0..63
            int kj = k0 + j;
            bool valid = kj < N_TOK;
            int fb = (t & 3) * 2;
            #pragma unroll
            for (int c = 0; c < 2; c++) {
                int f = fb + c;
                float4 kv = make_float4(0.f, 0.f, 0.f, 0.f);
                float4 vv = make_float4(0.f, 0.f, 0.f, 0.f);
                if (valid) {
                    kv = *(const float4*)(kptr + (size_t)kj * ODIM + f * 4);
                    vv = *(const float4*)(vptr + (size_t)kj * ODIM + f * 4);
                }
                int d = f * 4;
                Ks[(d + 0) * 64 + j] = kv.x;
                Ks[(d + 1) * 64 + j] = kv.y;
                Ks[(d + 2) * 64 + j] = kv.z;
                Ks[(d + 3) * 64 + j] = kv.w;
                *(float4*)&Vs[j * 32 + d] = vv;
            }
        }

        // ---- stage bias+mask into Ps (coalesced) ----
        #pragma unroll 8
        for (int u = 0; u < 32; u++) {
            int e  = u * 256 + t;
            int r  = e >> 6;
            int jc = e & 63;
            int qi = q0 + r;
            int kj = k0 + jc;
            float bm;
            if (qi >= N_TOK)      bm = 0.f;
            else if (kj >= N_TOK) bm = NEGBIG;
            else                  bm = brow[qi * N_TOK + kj] + mrow[qi * N_TOK + kj];
            Ps[r * 68 + jc] = bm;
        }
        __syncthreads();

        // ---- S = Q K^T (8x4 per thread) ----
        float s[8][4];
        #pragma unroll
        for (int i = 0; i < 8; i++)
            #pragma unroll
            for (int j = 0; j < 4; j++) s[i][j] = 0.f;

        #pragma unroll 8
        for (int d = 0; d < 32; d++) {
            float4 a0 = *(const float4*)&Qs[d * 128 + ty * 8];
            float4 a1 = *(const float4*)&Qs[d * 128 + ty * 8 + 4];
            float4 kv = *(const float4*)&Ks[d * 64 + tx * 4];
            float av[8] = {a0.x, a0.y, a0.z, a0.w, a1.x, a1.y, a1.z, a1.w};
            #pragma unroll
            for (int i = 0; i < 8; i++) {
                s[i][0] += av[i] * kv.x;
                s[i][1] += av[i] * kv.y;
                s[i][2] += av[i] * kv.z;
                s[i][3] += av[i] * kv.w;
            }
        }

        // ---- online softmax; P overwrites bias+mask (same owner thread) ----
        #pragma unroll
        for (int i = 0; i < 8; i++) {
            int r = ty * 8 + i;
            float sv0 = s[i][0] * SCALE + Ps[r * 68 + tx * 4 + 0];
            float sv1 = s[i][1] * SCALE + Ps[r * 68 + tx * 4 + 1];
            float sv2 = s[i][2] * SCALE + Ps[r * 68 + tx * 4 + 2];
            float sv3 = s[i][3] * SCALE + Ps[r * 68 + tx * 4 + 3];
            float tm = fmaxf(fmaxf(sv0, sv1), fmaxf(sv2, sv3));
            tm = fmaxf(tm, __shfl_xor_sync(0xffffffffu, tm, 1));
            tm = fmaxf(tm, __shfl_xor_sync(0xffffffffu, tm, 2));
            tm = fmaxf(tm, __shfl_xor_sync(0xffffffffu, tm, 4));
            tm = fmaxf(tm, __shfl_xor_sync(0xffffffffu, tm, 8));
            float mn = fmaxf(mrun[i], tm);
            float al = __expf(mrun[i] - mn);
            mrun[i] = mn;
            float4 p;
            p.x = __expf(sv0 - mn);
            p.y = __expf(sv1 - mn);
            p.z = __expf(sv2 - mn);
            p.w = __expf(sv3 - mn);
            float ts = (p.x + p.y) + (p.z + p.w);
            ts += __shfl_xor_sync(0xffffffffu, ts, 1);
            ts += __shfl_xor_sync(0xffffffffu, ts, 2);
            ts += __shfl_xor_sync(0xffffffffu, ts, 4);
            ts += __shfl_xor_sync(0xffffffffu, ts, 8);
            lrun[i] = lrun[i] * al + ts;
            *(float4*)&Ps[r * 68 + tx * 4] = p;
            if (tx == 0) Asm[r] = al;
        }
        __syncthreads();

        // ---- O = O*alpha + P V (4x4 per thread) ----
        {
            float al4[4];
            #pragma unroll
            for (int i = 0; i < 4; i++) al4[i] = Asm[pry * 4 + i];
            #pragma unroll
            for (int i = 0; i < 4; i++)
                #pragma unroll
                for (int c = 0; c < 4; c++) o[i][c] *= al4[i];

            #pragma unroll 8
            for (int j = 0; j < 64; j++) {
                float4 vv = *(const float4*)&Vs[j * 32 + pc * 4];
                #pragma unroll
                for (int i = 0; i < 4; i++) {
                    float p = Ps[(pry * 4 + i) * 68 + j];
                    o[i][0] += p * vv.x;
                    o[i][1] += p * vv.y;
                    o[i][2] += p * vv.z;
                    o[i][3] += p * vv.w;
                }
            }
        }
    }

    // ---- publish per-row l, normalize, store to [b, n, h, d] layout ----
    if (tx == 0) {
        #pragma unroll
        for (int i = 0; i < 8; i++) Lsm[ty * 8 + i] = lrun[i];
    }
    __syncthreads();

    #pragma unroll
    for (int i = 0; i < 4; i++) {
        int r  = pry * 4 + i;
        int qi = q0 + r;
        if (qi < N_TOK) {
            float inv = 1.f / Lsm[r];
            float4 ov = make_float4(o[i][0] * inv, o[i][1] * inv,
                                    o[i][2] * inv, o[i][3] * inv);
            *(float4*)&g_att[((size_t)b * N_TOK + qi) * CDIM + h * HDIM + pc * 4] = ov;
        }
    }
}

// ---------------- launch ----------------------------------------------------
extern "C" void kernel_launch(void* const* d_in, const int* in_sizes, int n_in,
                              void* d_out, int out_size) {
    (void)in_sizes; (void)n_in; (void)out_size;
    const float* x        = (const float*)d_in[0];
    const float* mask     = (const float*)d_in[1];
    const float* qkv_w    = (const float*)d_in[2];
    const float* proj_w   = (const float*)d_in[3];
    const float* proj_b   = (const float*)d_in[4];
    const float* bias_tab = (const float*)d_in[5];
    const int*   rel_idx  = (const int*)d_in[6];
    float* out = (float*)d_out;

    cudaFuncSetAttribute(attn_kernel,
                         cudaFuncAttributeMaxDynamicSharedMemorySize, 68608);
    cudaFuncSetAttribute(gemm_tc<0>,
                         cudaFuncAttributeMaxDynamicSharedMemorySize,
                         SM_GEMM_FLOATS * 4);
    cudaFuncSetAttribute(gemm_tc<1>,
                         cudaFuncAttributeMaxDynamicSharedMemorySize,
                         SM_GEMM_FLOATS * 4);

    bias_gather_kernel<<<(NN2 + 255) / 256, 256>>>(bias_tab, rel_idx);
    gemm_tc<0><<<dim3(ODIM / 64, MROWS / 128), 256, SM_GEMM_FLOATS * 4>>>(
        x, qkv_w, nullptr, nullptr, ODIM);
    attn_kernel<<<dim3(3, HEADS, BATCH), 256, 68608>>>(mask);
    gemm_tc<1><<<dim3(CDIM / 64, MROWS / 128), 256, SM_GEMM_FLOATS * 4>>>(
        nullptr, proj_w, proj_b, out, CDIM);
}